// round 17
// baseline (speedup 1.0000x reference)
#include <cuda_runtime.h>
#include <cuda_fp16.h>
#include <cstdint>

// Problem constants
#define BATCH   32
#define HID     1024
#define NGATE   4096          // 4*HID
#define TSTEPS  511           // T-1
#define MTOT    16352         // TSTEPS*BATCH
#define RES_ELEMS (511*32*1024)

// ---------------- device scratch (no runtime allocation allowed) -------------
__device__ unsigned g_hp[2][64 * 32 * 8];          // h double-buffered, fp16 frag-packed
__device__ unsigned g_cnt;                         // single barrier counter (reset by prea)
// gathered emb, fp16, packed per-t in the SAME fragment layout as g_hp:
// g_af[t*16384 + hp16_index(b,k)]  (33.5 MB -> L2-resident working set)
__device__ __align__(16) unsigned g_af[(size_t)TSTEPS * 16384];

// ---------------- small helpers ----------------------------------------------
__device__ __forceinline__ uint4 ldcg4(const unsigned* p) {
    uint4 v;
    asm volatile("ld.global.cg.v4.u32 {%0,%1,%2,%3}, [%4];"
                 : "=r"(v.x), "=r"(v.y), "=r"(v.z), "=r"(v.w) : "l"(p));
    return v;
}
__device__ __forceinline__ unsigned ldacq(const unsigned* p) {
    unsigned v;
    asm volatile("ld.acquire.gpu.global.u32 %0, [%1];" : "=r"(v) : "l"(p));
    return v;
}
// fire-and-forget release reduction (fence folded into the atomic)
__device__ __forceinline__ void red_release_add(unsigned* p, unsigned v) {
    asm volatile("red.release.gpu.global.add.u32 [%0], %1;" :: "l"(p), "r"(v) : "memory");
}
// fp16 mma
__device__ __forceinline__ void mma16(float c[4], unsigned a0, unsigned a1, unsigned a2,
                                      unsigned a3, unsigned b0, unsigned b1) {
    asm volatile(
        "mma.sync.aligned.m16n8k16.row.col.f32.f16.f16.f32 "
        "{%0,%1,%2,%3}, {%4,%5,%6,%7}, {%8,%9}, {%0,%1,%2,%3};"
        : "+f"(c[0]), "+f"(c[1]), "+f"(c[2]), "+f"(c[3])
        : "r"(a0), "r"(a1), "r"(a2), "r"(a3), "r"(b0), "r"(b1));
}
__device__ __forceinline__ unsigned pack_h2(float x, float y) {
    __half2 h = __floats2half2_rn(x, y);
    return *(unsigned*)&h;
}
__device__ __forceinline__ float fsig(float x) {
    return __fdividef(1.f, 1.f + __expf(-x));
}
__device__ __forceinline__ float ftanh(float x) {
    return __fmaf_rn(2.f, fsig(2.f * x), -1.f);
}
// fp16 fragment-pack u32-slot index for h element (b, k); (k&1) selects the half.
__device__ __forceinline__ int hp16_index(int b, int k) {
    int kb   = k >> 4;
    int d    = (k >> 3) & 1;
    int tg   = (k >> 1) & 3;
    int g    = b & 7;
    int q    = b >> 3;
    int slot = ((q >> 1) << 2) | (d << 1) | (q & 1);
    int ln   = g * 4 + tg;
    return (kb * 32 + ln) * 8 + slot;
}

// ---------------- pre-pass: gather emb -> g_af (per-t fragment layout) --------
// One u32 (= one fp16 pair) per thread. Also resets the lstm barrier counter.
__global__ void __launch_bounds__(256)
prea_kernel(const int* __restrict__ tgt, const float* __restrict__ emb)
{
    if (blockIdx.x == 0 && threadIdx.x == 0) g_cnt = 0u;
    int idx = blockIdx.x * 256 + threadIdx.x;      // MTOT*512 total
    int mg = idx >> 9;                             // global m row (t*32+b), < 16352
    int p  = idx & 511;                            // k-pair 0..511
    if (mg >= MTOT) return;
    int bb = mg & 31, tt = mg >> 5;                // b, t
    int tok = tgt[bb * 512 + tt];
    if (tok < 0 || tok > 31999) tok = 0;
    unsigned val = pack_h2(emb[(size_t)tok * 1024 + 2 * p],
                           emb[(size_t)tok * 1024 + 2 * p + 1]);
    g_af[(size_t)tt * 16384 + hp16_index(bb, 2 * p)] = val;
}

// ---------------- persistent fused kernel ------------------------------------
// 128 CTAs x 256 threads (R14 structure; sync scheme frozen).
// CTA c owns hidden units [c*8, c*8+8). NEW: the x-projection slice this CTA's
// gates need is computed INLINE each step (same 32x32x1024 mma shape as the
// h-recurrence, A = g_af[t] in identical fragment layout, B = W_ih fragments
// in registers). It is h-independent, so it runs BEFORE the barrier poll and
// fills the wait window. No g_xp array, no separate GEMM launch.
__global__ void __launch_bounds__(256, 1)
lstm_kernel(const float* __restrict__ h0, const float* __restrict__ c0,
            const float* __restrict__ W_hh, const float* __restrict__ W_ih,
            const float* __restrict__ b_ih, const float* __restrict__ b_hh,
            float* __restrict__ out, int out_size)
{
    extern __shared__ float sh[];
    float* red1  = sh;            // 8448 floats: h-partials   (m*33+n)*8+wid
    float* red2  = sh + 8448;     // 8448 floats: xp-partials  (same indexing)
    float* stage = sh + 16896;    // 256 floats: hv staging for coalesced out

    const int tid = threadIdx.x, lane = tid & 31, wid = tid >> 5;
    const int g = lane >> 2, tg = lane & 3;
    const int j0 = blockIdx.x * 8;
    const int b = tid >> 3, jj = tid & 7;           // this thread's cell (b, j0+jj)

    // ---- load W_hh and W_ih fragments into registers (fp16 pairs) ----
    unsigned bw[8][4][2], bx[8][4][2];
#pragma unroll
    for (int s = 0; s < 8; ++s) {
#pragma unroll
        for (int nt = 0; nt < 4; ++nt) {
            int r = nt * 8 + g;                 // local gate-row 0..31
            int q = r >> 3, jr = r & 7;
            size_t off = (size_t)(q * 1024 + j0 + jr) * 1024 + wid * 128 + s * 16;
            const float* wh = W_hh + off;
            bw[s][nt][0] = pack_h2(wh[2 * tg],     wh[2 * tg + 1]);
            bw[s][nt][1] = pack_h2(wh[8 + 2 * tg], wh[8 + 2 * tg + 1]);
            const float* wi = W_ih + off;
            bx[s][nt][0] = pack_h2(wi[2 * tg],     wi[2 * tg + 1]);
            bx[s][nt][1] = pack_h2(wi[8 + 2 * tg], wi[8 + 2 * tg + 1]);
        }
    }

    // per-thread gate biases (independent of b)
    float bias[4];
#pragma unroll
    for (int q = 0; q < 4; ++q)
        bias[q] = b_ih[q * 1024 + j0 + jj] + b_hh[q * 1024 + j0 + jj];

    float c_reg = c0[b * 1024 + j0 + jj];

    // own h u32 slot (paired: jj-even thread stores both halves for jj, jj+1)
    const int hk     = j0 + jj;
    const int hp_idx = hp16_index(b, hk);

    // ---- prologue: pack own h0 slice (paired 4B stores), arrive ----
    {
        __half hh = __float2half(h0[b * 1024 + hk]);
        unsigned hu = (unsigned)__half_as_ushort(hh);
        unsigned up = __shfl_down_sync(0xffffffffu, hu, 1);
        if ((jj & 1) == 0) g_hp[0][hp_idx] = hu | (up << 16);
    }
    __syncthreads();
    if (tid == 0) red_release_add(&g_cnt, 1u);

    for (int t = 0; t < TSTEPS; ++t) {
        // ---------- (a) xp phase: h-independent, fills the wait window ------
        {
            const unsigned* ab = g_af + (size_t)t * 16384;
            float X[8][4];
#pragma unroll
            for (int i = 0; i < 8; ++i) { X[i][0] = 0.f; X[i][1] = 0.f; X[i][2] = 0.f; X[i][3] = 0.f; }
#pragma unroll
            for (int s = 0; s < 8; ++s) {
                const unsigned* p = ab + ((wid * 8 + s) * 32 + lane) * 8;
                uint4 A0 = ldcg4(p);        // batches 0..15
                uint4 A1 = ldcg4(p + 4);    // batches 16..31
#pragma unroll
                for (int nt = 0; nt < 4; ++nt) {
                    mma16(X[nt],     A0.x, A0.y, A0.z, A0.w, bx[s][nt][0], bx[s][nt][1]);
                    mma16(X[4 + nt], A1.x, A1.y, A1.z, A1.w, bx[s][nt][0], bx[s][nt][1]);
                }
            }
#pragma unroll
            for (int mt = 0; mt < 2; ++mt) {
#pragma unroll
                for (int nt = 0; nt < 4; ++nt) {
                    float* cc = X[mt * 4 + nt];
                    int m  = mt * 16 + g;
                    int n0 = nt * 8 + tg * 2;
                    red2[((m)     * 33 + n0    ) * 8 + wid] = cc[0];
                    red2[((m)     * 33 + n0 + 1) * 8 + wid] = cc[1];
                    red2[((m + 8) * 33 + n0    ) * 8 + wid] = cc[2];
                    red2[((m + 8) * 33 + n0 + 1) * 8 + wid] = cc[3];
                }
            }
        }

        // ---------- (b) wait until all 128 CTAs published h_t ---------------
        if (tid == 0) {
            const unsigned target = 128u * (unsigned)(t + 1);
            while ((int)(ldacq(&g_cnt) - target) < 0) { }
        }
        __syncthreads();   // (c) barrier release + red2 partials visible

        // ---------- (d) h phase: warp wid owns k16 blocks wid*8..+7 ---------
        const unsigned* hb = g_hp[t & 1];
        float C[8][4];
#pragma unroll
        for (int i = 0; i < 8; ++i) { C[i][0] = 0.f; C[i][1] = 0.f; C[i][2] = 0.f; C[i][3] = 0.f; }

#pragma unroll
        for (int s = 0; s < 8; ++s) {
            const unsigned* p = hb + ((wid * 8 + s) * 32 + lane) * 8;
            uint4 A0 = ldcg4(p);        // batches 0..15
            uint4 A1 = ldcg4(p + 4);    // batches 16..31
#pragma unroll
            for (int nt = 0; nt < 4; ++nt) {
                mma16(C[nt],     A0.x, A0.y, A0.z, A0.w, bw[s][nt][0], bw[s][nt][1]);
                mma16(C[4 + nt], A1.x, A1.y, A1.z, A1.w, bw[s][nt][0], bw[s][nt][1]);
            }
        }

#pragma unroll
        for (int mt = 0; mt < 2; ++mt) {
#pragma unroll
            for (int nt = 0; nt < 4; ++nt) {
                float* cc = C[mt * 4 + nt];
                int m  = mt * 16 + g;
                int n0 = nt * 8 + tg * 2;
                red1[((m)     * 33 + n0    ) * 8 + wid] = cc[0];
                red1[((m)     * 33 + n0 + 1) * 8 + wid] = cc[1];
                red1[((m + 8) * 33 + n0    ) * 8 + wid] = cc[2];
                red1[((m + 8) * 33 + n0 + 1) * 8 + wid] = cc[3];
            }
        }
        __syncthreads();   // (e) h-partials visible

        // ---------- gate math: one thread per (b, jj) -----------------------
        float z[4];
#pragma unroll
        for (int q = 0; q < 4; ++q) {
            int r = q * 8 + jj;
            const float4* p1 = (const float4*)&red1[(b * 33 + r) * 8];
            const float4* p2 = (const float4*)&red2[(b * 33 + r) * 8];
            float4 s0 = p1[0], s1 = p1[1];
            float4 u0 = p2[0], u1 = p2[1];
            float hsum = ((s0.x + s0.y) + (s0.z + s0.w)) + ((s1.x + s1.y) + (s1.z + s1.w));
            float xsum = ((u0.x + u0.y) + (u0.z + u0.w)) + ((u1.x + u1.y) + (u1.z + u1.w));
            z[q] = bias[q] + xsum + hsum;
        }
        float iv = fsig(z[0]);
        float fv = fsig(z[1]);
        float gv = ftanh(z[2]);
        float ov = fsig(z[3]);
        c_reg = fv * c_reg + iv * gv;
        float hv = ov * ftanh(c_reg);

        if (t < TSTEPS - 1) {
            // stage hv; publish packed h_{t+1} (paired 4B stores); then arrive
            stage[tid] = hv;
            __half hh = __float2half(hv);
            unsigned hu = (unsigned)__half_as_ushort(hh);
            unsigned up = __shfl_down_sync(0xffffffffu, hu, 1);
            if ((jj & 1) == 0) g_hp[(t + 1) & 1][hp_idx] = hu | (up << 16);
            __syncthreads();   // (h) h + stage visible; red1/red2 reuse safety
            if (tid == 0) red_release_add(&g_cnt, 1u);
            // coalesced out stores (off the critical path, overlap next wait)
            if (tid < 64) {
                int bb = tid >> 1, half = tid & 1;
                float4 v = *(const float4*)&stage[bb * 8 + half * 4];
                float* dst = out + ((size_t)bb * TSTEPS + t) * 1024 + j0 + half * 4;
                __stcs((float4*)dst, v);
            }
        } else {
            __stcs(out + ((size_t)b * TSTEPS + t) * 1024 + j0 + jj, hv);
            if (out_size >= RES_ELEMS + 2 * BATCH * HID) {
                out[RES_ELEMS + b * 1024 + j0 + jj]               = hv;     // hT
                out[RES_ELEMS + BATCH * HID + b * 1024 + j0 + jj] = c_reg;  // cT
            }
        }
    }
}

// ---------------- launch ------------------------------------------------------
extern "C" void kernel_launch(void* const* d_in, const int* in_sizes, int n_in,
                              void* d_out, int out_size)
{
    const int*   tgt  = (const int*)  d_in[0];
    const float* h0   = (const float*)d_in[1];
    const float* c0   = (const float*)d_in[2];
    // d_in[3] encoder_outputs, d_in[4] src_lengths: unused by the reference
    const float* emb  = (const float*)d_in[5];
    const float* W_ih = (const float*)d_in[6];
    const float* W_hh = (const float*)d_in[7];
    const float* b_ih = (const float*)d_in[8];
    const float* b_hh = (const float*)d_in[9];
    float* out = (float*)d_out;

    const int lstm_smem = (8448 + 8448 + 256) * 4;   // red1 + red2 + stage = 68608 B
    cudaFuncSetAttribute(lstm_kernel, cudaFuncAttributeMaxDynamicSharedMemorySize,
                         lstm_smem);

    // gather emb -> per-t fragment tiles (+ barrier counter reset)
    prea_kernel<<<(MTOT * 512 + 255) / 256, 256>>>(tgt, emb);

    lstm_kernel<<<128, 256, lstm_smem>>>(h0, c0, W_hh, W_ih, b_ih, b_hh,
                                         out, out_size);
}